// round 12
// baseline (speedup 1.0000x reference)
#include <cuda_runtime.h>

// out = M rho M^T on the Hamming-weight-2 basis (N = C(32,2) = 496).
// M block-diagonal over 36 pair-blocks; TWO distinct 4x4 tile matrices
// (V_row: params 0-5, V_col: params 6-11), pyramid order {0,1,0,2,1,0}.
//   cross block (t1<t2): dim 16, B = V_t1 (x) V_t2
//   diag  block (t):     dim 6,  B = Lambda^2(V_t) (inline)
// SYMMETRY: compute only I <= J (666 blocks), mirror out[J,I] = out[I,J]^T.
// WARP-SYNCHRONOUS: one warp per block, 8 elements/lane in registers, all
// mixing via shfl_xor butterflies. Zero __syncthreads; 4 warps packed per CTA.

#define NP 496
#define FM 0xFFFFFFFFu

__device__ __forceinline__ int pair_idx(int a, int b) {
    return a * 31 - (a * (a - 1)) / 2 + (b - a - 1);
}

__device__ __forceinline__ void decode_block(int B, int& t1, int& t2, int& dim) {
    if (B < 28) {
        int rem = B, a = 0;
        while (rem >= 7 - a) { rem -= 7 - a; a++; }
        t1 = a; t2 = a + 1 + rem; dim = 16;
    } else {
        t1 = B - 28; t2 = t1; dim = 6;
    }
}

__device__ __forceinline__ int tri_base(int I) { return (73 * I - I * I) >> 1; }

// P1 = {0,0,0,1,1,2}, P2 = {1,2,3,2,3,3}, 3 bits/entry
#define P1W 0x11200
#define P2W 0x1B4D1
__device__ __forceinline__ int p1of(int m) { return (P1W >> (3 * m)) & 7; }
__device__ __forceinline__ int p2of(int m) { return (P2W >> (3 * m)) & 7; }

template <int D>
__device__ __forceinline__ int gidx(int t1, int t2, int m) {
    if (D == 16) return pair_idx(4 * t1 + (m >> 2), 4 * t2 + (m & 3));
    return pair_idx(4 * t1 + p1of(m), 4 * t1 + p2of(m));
}

__device__ __forceinline__ float went(const float* U, int m, int n) {
    int a = p1of(m), b = p2of(m), g = p1of(n), d = p2of(n);
    return U[a * 4 + g] * U[b * 4 + d] - U[a * 4 + d] * U[b * 4 + g];
}

// One warp composes BOTH tile matrices: half-warp h builds V for param group h.
// Lane h*16+idx ends holding V[h][idx]; written to warp-private sVw[32].
__device__ __forceinline__ void compose_V_warp(int lane, const float* __restrict__ thetas,
                                               float* sVw) {
    const int h = lane >> 4, idx = lane & 15;
    float s, c;
    sincosf(__ldg(thetas + h * 6 + (idx % 6)), &s, &c);
    const int r = idx >> 2;
    float v = ((idx >> 2) == (idx & 3)) ? 1.f : 0.f;
    const int jseq[6] = {0, 1, 0, 2, 1, 0};
    #pragma unroll
    for (int gi = 0; gi < 6; gi++) {
        const int j = jseq[gi];
        const int src = (lane & 16) + gi;
        float cg = __shfl_sync(FM, c, src);
        float sg = __shfl_sync(FM, s, src);
        float vu = __shfl_sync(FM, v, (lane + 4) & 31);
        float vd = __shfl_sync(FM, v, (lane - 4) & 31);
        if (r == j)          v = cg * v + sg * vu;
        else if (r == j + 1) v = cg * v - sg * vd;
    }
    sVw[lane] = v;
}

__device__ __forceinline__ float4 shflx4(float4 a, int m) {
    float4 r;
    r.x = __shfl_xor_sync(FM, a.x, m);
    r.y = __shfl_xor_sync(FM, a.y, m);
    r.z = __shfl_xor_sync(FM, a.z, m);
    r.w = __shfl_xor_sync(FM, a.w, m);
    return r;
}

__device__ __forceinline__ float4 f4fma(float4 acc, float w, float4 x) {
    acc.x += w * x.x; acc.y += w * x.y; acc.z += w * x.z; acc.w += w * x.w;
    return acc;
}
__device__ __forceinline__ float4 f4mul(float w, float4 x) {
    return make_float4(w * x.x, w * x.y, w * x.z, w * x.w);
}

// ----- cross x cross (16x16) : pure register + shuffle, no smem data --------
__device__ __forceinline__ void warp_cross16(
    const float* __restrict__ rho, float* __restrict__ out,
    const float* __restrict__ thetas,
    int T1, int T2, int t1, int t2, int lane, bool mirror, float* sVw)
{
    const int m_lo = lane >> 2, g = lane & 3;
    const int grow0 = gidx<16>(T1, T2, m_lo);
    const int grow1 = gidx<16>(T1, T2, m_lo + 8);
    const int colbase = pair_idx(4 * t1 + g, 4 * t2);

    // early gather: 8 scalar LDG (rows m_lo, m_lo+8, cols colbase..+3)
    float4 x0, x1;
    {
        const float* p0 = rho + grow0 * NP + colbase;
        const float* p1 = rho + grow1 * NP + colbase;
        x0.x = __ldg(p0);     x0.y = __ldg(p0 + 1);
        x0.z = __ldg(p0 + 2); x0.w = __ldg(p0 + 3);
        x1.x = __ldg(p1);     x1.y = __ldg(p1 + 1);
        x1.z = __ldg(p1 + 2); x1.w = __ldg(p1 + 3);
    }
    compose_V_warp(lane, thetas, sVw);   // overlaps the gather
    __syncwarp();

    const float* V1 = sVw + (T1 >> 2) * 16;
    const float* V2 = sVw + (T2 >> 2) * 16;
    const float* U1 = sVw + (t1 >> 2) * 16;
    const float* U2 = sVw + (t2 >> 2) * 16;

    // LEFT stage 1: be-mix (row bits within tile T2) via masks 4,8,12
    const int be = m_lo & 3;
    const float cb0 = V2[be * 4 + be];
    const float cb1 = V2[be * 4 + (be ^ 1)];
    const float cb2 = V2[be * 4 + (be ^ 2)];
    const float cb3 = V2[be * 4 + (be ^ 3)];
    float4 y0 = f4mul(cb0, x0);
    y0 = f4fma(y0, cb1, shflx4(x0, 4));
    y0 = f4fma(y0, cb2, shflx4(x0, 8));
    y0 = f4fma(y0, cb3, shflx4(x0, 12));
    float4 y1 = f4mul(cb0, x1);
    y1 = f4fma(y1, cb1, shflx4(x1, 4));
    y1 = f4fma(y1, cb2, shflx4(x1, 8));
    y1 = f4fma(y1, cb3, shflx4(x1, 12));

    // LEFT stage 2: al-mix (tile T1) via mask 16 + register pair
    const int a0 = m_lo >> 2;            // 0 or 1 ; reg0 al=a0, reg1 al=a0+2
    float4 s0 = shflx4(y0, 16);
    float4 s1 = shflx4(y1, 16);
    const int a1 = a0 ^ 1;
    float4 z0 = f4mul(V1[a0 * 4 + a0], y0);
    z0 = f4fma(z0, V1[a0 * 4 + a1],     s0);
    z0 = f4fma(z0, V1[a0 * 4 + a0 + 2], y1);
    z0 = f4fma(z0, V1[a0 * 4 + a1 + 2], s1);
    const int a2 = a0 + 2;
    float4 z1 = f4mul(V1[a2 * 4 + a0], y0);
    z1 = f4fma(z1, V1[a2 * 4 + a1],     s0);
    z1 = f4fma(z1, V1[a2 * 4 + a0 + 2], y1);
    z1 = f4fma(z1, V1[a2 * 4 + a1 + 2], s1);

    // RIGHT stage A: de-mix (tile t2), local within the float4
    float4 w0, w1;
    w0.x = U2[0]  * z0.x + U2[1]  * z0.y + U2[2]  * z0.z + U2[3]  * z0.w;
    w0.y = U2[4]  * z0.x + U2[5]  * z0.y + U2[6]  * z0.z + U2[7]  * z0.w;
    w0.z = U2[8]  * z0.x + U2[9]  * z0.y + U2[10] * z0.z + U2[11] * z0.w;
    w0.w = U2[12] * z0.x + U2[13] * z0.y + U2[14] * z0.z + U2[15] * z0.w;
    w1.x = U2[0]  * z1.x + U2[1]  * z1.y + U2[2]  * z1.z + U2[3]  * z1.w;
    w1.y = U2[4]  * z1.x + U2[5]  * z1.y + U2[6]  * z1.z + U2[7]  * z1.w;
    w1.z = U2[8]  * z1.x + U2[9]  * z1.y + U2[10] * z1.z + U2[11] * z1.w;
    w1.w = U2[12] * z1.x + U2[13] * z1.y + U2[14] * z1.z + U2[15] * z1.w;

    // RIGHT stage B: g-mix (tile t1) via masks 1,2,3
    const float cg0 = U1[g * 4 + g];
    const float cg1 = U1[g * 4 + (g ^ 1)];
    const float cg2 = U1[g * 4 + (g ^ 2)];
    const float cg3 = U1[g * 4 + (g ^ 3)];
    float4 o0 = f4mul(cg0, w0);
    o0 = f4fma(o0, cg1, shflx4(w0, 1));
    o0 = f4fma(o0, cg2, shflx4(w0, 2));
    o0 = f4fma(o0, cg3, shflx4(w0, 3));
    float4 o1 = f4mul(cg0, w1);
    o1 = f4fma(o1, cg1, shflx4(w1, 1));
    o1 = f4fma(o1, cg2, shflx4(w1, 2));
    o1 = f4fma(o1, cg3, shflx4(w1, 3));

    // store (+ transposed mirror)
    {
        float* p0 = out + grow0 * NP + colbase;
        float* p1 = out + grow1 * NP + colbase;
        p0[0] = o0.x; p0[1] = o0.y; p0[2] = o0.z; p0[3] = o0.w;
        p1[0] = o1.x; p1[1] = o1.y; p1[2] = o1.z; p1[3] = o1.w;
    }
    if (mirror) {
        out[(colbase + 0) * NP + grow0] = o0.x;
        out[(colbase + 1) * NP + grow0] = o0.y;
        out[(colbase + 2) * NP + grow0] = o0.z;
        out[(colbase + 3) * NP + grow0] = o0.w;
        out[(colbase + 0) * NP + grow1] = o1.x;
        out[(colbase + 1) * NP + grow1] = o1.y;
        out[(colbase + 2) * NP + grow1] = o1.z;
        out[(colbase + 3) * NP + grow1] = o1.w;
    }
}

// ----- J diagonal (DI x 6): warp-private smem, __syncwarp only --------------
template <int DI>
__device__ __forceinline__ void warp_jdiag(
    const float* __restrict__ rho, float* __restrict__ out,
    const float* __restrict__ thetas,
    int T1, int T2, int t1, int lane, bool mirror,
    float* sVw, float (*bA)[8], float (*bB)[8])
{
    float rs[3];
    #pragma unroll
    for (int k = 0; k < 3; k++) {
        int e = lane + 32 * k;
        if (e < DI * 6)
            rs[k] = __ldg(rho + gidx<DI>(T1, T2, e / 6) * NP + gidx<6>(t1, t1, e % 6));
    }
    compose_V_warp(lane, thetas, sVw);
    #pragma unroll
    for (int k = 0; k < 3; k++) {
        int e = lane + 32 * k;
        if (e < DI * 6) bA[e / 6][e % 6] = rs[k];
    }
    __syncwarp();

    const float* V1 = sVw + (T1 >> 2) * 16;
    const float* V2 = sVw + (T2 >> 2) * 16;
    #pragma unroll
    for (int k = 0; k < 3; k++) {
        int e = lane + 32 * k;
        if (e < DI * 6) {
            int m = e / 6, c = e % 6;
            float acc = 0.f;
            if (DI == 16) {
                const int al = m >> 2, bee = m & 3;
                #pragma unroll
                for (int ap = 0; ap < 4; ap++) {
                    float s2 = 0.f;
                    #pragma unroll
                    for (int bp = 0; bp < 4; bp++)
                        s2 += V2[bee * 4 + bp] * bA[ap * 4 + bp][c];
                    acc += V1[al * 4 + ap] * s2;
                }
            } else {
                #pragma unroll
                for (int n = 0; n < 6; n++)
                    acc += went(V1, m, n) * bA[n][c];
            }
            bB[m][c] = acc;
        }
    }
    __syncwarp();

    const float* UJ = sVw + (t1 >> 2) * 16;
    #pragma unroll
    for (int k = 0; k < 3; k++) {
        int e = lane + 32 * k;
        if (e < DI * 6) {
            int m = e / 6, c = e % 6;
            float acc = 0.f;
            #pragma unroll
            for (int n = 0; n < 6; n++)
                acc += went(UJ, c, n) * bB[m][n];
            const int gr = gidx<DI>(T1, T2, m);
            const int gc = gidx<6>(t1, t1, c);
            out[gr * NP + gc] = acc;
            if (mirror) out[gc * NP + gr] = acc;
        }
    }
}

__global__ void __launch_bounds__(128, 8)
rbs_kernel(const float* __restrict__ rho, float* __restrict__ out,
           const float* __restrict__ thetas)
{
    __shared__ __align__(16) float sVw[4][32];
    __shared__ __align__(16) float bufs[4][2][16][8];

    const int w = threadIdx.x >> 5, lane = threadIdx.x & 31;
    const int k = blockIdx.x * 4 + w;
    if (k >= 666) return;

    // decode upper-triangular pair (I <= J)
    int I = (int)((73.0f - sqrtf(5329.0f - 8.0f * (float)k)) * 0.5f);
    while (tri_base(I + 1) <= k) ++I;
    while (tri_base(I) > k) --I;
    const int J = I + (k - tri_base(I));
    const bool mirror = (I != J);

    int T1, T2, DI, t1, t2, DJ;
    decode_block(I, T1, T2, DI);
    decode_block(J, t1, t2, DJ);

    if (DJ == 16) {
        // I <= J and J cross => I cross too
        warp_cross16(rho, out, thetas, T1, T2, t1, t2, lane, mirror, sVw[w]);
    } else if (DI == 16) {
        warp_jdiag<16>(rho, out, thetas, T1, T2, t1, lane, mirror,
                       sVw[w], bufs[w][0], bufs[w][1]);
    } else {
        warp_jdiag< 6>(rho, out, thetas, T1, T2, t1, lane, mirror,
                       sVw[w], bufs[w][0], bufs[w][1]);
    }
}

extern "C" void kernel_launch(void* const* d_in, const int* in_sizes, int n_in,
                              void* d_out, int out_size) {
    // metadata order: rho, thetas, A_stack, B_stack, C_stack, u_idx, p_idx
    const float* rho    = (const float*)d_in[0];
    const float* thetas = (const float*)d_in[1];
    float* out = (float*)d_out;

    rbs_kernel<<<(666 + 3) / 4, 128>>>(rho, out, thetas);
}

// round 13
// speedup vs baseline: 1.0386x; 1.0386x over previous
#include <cuda_runtime.h>

// out = M rho M^T on the Hamming-weight-2 basis (N = C(32,2) = 496).
// M block-diagonal over 36 pair-blocks; TWO distinct 4x4 tile matrices
// (V_row: params 0-5, V_col: params 6-11), pyramid order {0,1,0,2,1,0}.
//   cross block (t1<t2): dim 16, B = V_t1 (x) V_t2
//   diag  block (t):     dim 6,  B = Lambda^2(V_t) = W
// SYMMETRY: compute only I <= J (666 CTAs), mirror out[J,I] = out[I,J]^T.
// Cross path: 2 warps/block, x in registers, be-mix via butterflies,
// al-mix via ONE float4 smem exchange (1 STS + 2 LDS), 1 barrier.
// Each warp composes BOTH V matrices privately (no compose barrier).

#define NP 496
#define FM 0xFFFFFFFFu

__device__ __forceinline__ int pair_idx(int a, int b) {
    return a * 31 - (a * (a - 1)) / 2 + (b - a - 1);
}

__device__ __forceinline__ void decode_block(int B, int& t1, int& t2, int& dim) {
    if (B < 28) {
        int rem = B, a = 0;
        while (rem >= 7 - a) { rem -= 7 - a; a++; }
        t1 = a; t2 = a + 1 + rem; dim = 16;
    } else {
        t1 = B - 28; t2 = t1; dim = 6;
    }
}

__device__ __forceinline__ int tri_base(int I) { return (73 * I - I * I) >> 1; }

// P1 = {0,0,0,1,1,2}, P2 = {1,2,3,2,3,3}, 3 bits/entry
#define P1W 0x11200
#define P2W 0x1B4D1
__device__ __forceinline__ int p1of(int m) { return (P1W >> (3 * m)) & 7; }
__device__ __forceinline__ int p2of(int m) { return (P2W >> (3 * m)) & 7; }

template <int D>
__device__ __forceinline__ int gidx(int t1, int t2, int m) {
    if (D == 16) return pair_idx(4 * t1 + (m >> 2), 4 * t2 + (m & 3));
    return pair_idx(4 * t1 + p1of(m), 4 * t1 + p2of(m));
}

// One warp composes BOTH tile matrices: half-warp h builds group h.
// Lane h*16+idx ends holding V[h][idx]; written to warp-private sVw[32].
__device__ __forceinline__ void compose_V_warp(int lane, const float* __restrict__ thetas,
                                               float* sVw) {
    const int h = lane >> 4, idx = lane & 15;
    float s, c;
    sincosf(__ldg(thetas + h * 6 + (idx % 6)), &s, &c);
    const int r = idx >> 2;
    float v = ((idx >> 2) == (idx & 3)) ? 1.f : 0.f;
    const int jseq[6] = {0, 1, 0, 2, 1, 0};
    #pragma unroll
    for (int gi = 0; gi < 6; gi++) {
        const int j = jseq[gi];
        const int src = (lane & 16) + gi;
        float cg = __shfl_sync(FM, c, src);
        float sg = __shfl_sync(FM, s, src);
        float vu = __shfl_sync(FM, v, (lane + 4) & 31);
        float vd = __shfl_sync(FM, v, (lane - 4) & 31);
        if (r == j)          v = cg * v + sg * vu;
        else if (r == j + 1) v = cg * v - sg * vd;
    }
    sVw[lane] = v;
}

__device__ __forceinline__ float4 shflx4(float4 a, int m) {
    float4 r;
    r.x = __shfl_xor_sync(FM, a.x, m);
    r.y = __shfl_xor_sync(FM, a.y, m);
    r.z = __shfl_xor_sync(FM, a.z, m);
    r.w = __shfl_xor_sync(FM, a.w, m);
    return r;
}
__device__ __forceinline__ float4 f4fma(float4 acc, float w, float4 x) {
    acc.x += w * x.x; acc.y += w * x.y; acc.z += w * x.z; acc.w += w * x.w;
    return acc;
}
__device__ __forceinline__ float4 f4mul(float w, float4 x) {
    return make_float4(w * x.x, w * x.y, w * x.z, w * x.w);
}

// ---- cross x cross (16x16): 2 warps, registers + butterflies + 1 exchange --
__device__ __forceinline__ void path_cross16(
    const float* __restrict__ rho, float* __restrict__ out,
    const float* __restrict__ thetas,
    int T1, int T2, int t1, int t2, int tid, bool mirror,
    float (*sVw)[32], float4* sY)
{
    const int w = tid >> 5, lane = tid & 31;
    const int m = tid >> 2, g = tid & 3;      // row m (0..15), col group g
    const int al = m >> 2;                    // lane bit4 = al&1, warp = al>>1
    const int be = m & 3;                     // lane bits 2,3

    const int grow = gidx<16>(T1, T2, m);
    const int colbase = pair_idx(4 * t1 + g, 4 * t2);

    // early gather (4 consecutive floats of row grow)
    float4 x;
    {
        const float* p = rho + grow * NP + colbase;
        x.x = __ldg(p); x.y = __ldg(p + 1); x.z = __ldg(p + 2); x.w = __ldg(p + 3);
    }
    float* sV = sVw[w];
    compose_V_warp(lane, thetas, sV);         // overlaps gather; warp-private
    __syncwarp();

    const float* V1 = sV + (T1 >> 2) * 16;
    const float* V2 = sV + (T2 >> 2) * 16;
    const float* U1 = sV + (t1 >> 2) * 16;
    const float* U2 = sV + (t2 >> 2) * 16;

    // LEFT stage 1 (be-mix, within warp; be = lane bits 2,3 -> masks 4,8,12)
    float4 y = f4mul(V2[be * 4 + be], x);
    y = f4fma(y, V2[be * 4 + (be ^ 1)], shflx4(x, 4));
    y = f4fma(y, V2[be * 4 + (be ^ 2)], shflx4(x, 8));
    y = f4fma(y, V2[be * 4 + (be ^ 3)], shflx4(x, 12));

    // al^1 partner within warp (lane bit4)
    float4 y1 = shflx4(y, 16);

    // exchange with other warp for al^2, al^3
    sY[tid] = y;
    __syncthreads();
    float4 y2 = sY[(1 - w) * 32 + lane];
    float4 y3 = sY[(1 - w) * 32 + (lane ^ 16)];

    // LEFT stage 2 (al-mix)
    float4 z = f4mul(V1[al * 4 + al], y);
    z = f4fma(z, V1[al * 4 + (al ^ 1)], y1);
    z = f4fma(z, V1[al * 4 + (al ^ 2)], y2);
    z = f4fma(z, V1[al * 4 + (al ^ 3)], y3);

    // RIGHT stage A (de-mix, local within float4; U2 row-major [de'][de])
    float4 w4;
    w4.x = U2[0]  * z.x + U2[1]  * z.y + U2[2]  * z.z + U2[3]  * z.w;
    w4.y = U2[4]  * z.x + U2[5]  * z.y + U2[6]  * z.z + U2[7]  * z.w;
    w4.z = U2[8]  * z.x + U2[9]  * z.y + U2[10] * z.z + U2[11] * z.w;
    w4.w = U2[12] * z.x + U2[13] * z.y + U2[14] * z.z + U2[15] * z.w;

    // RIGHT stage B (ga-mix; g = lane bits 0,1 -> masks 1,2,3)
    float4 o = f4mul(U1[g * 4 + g], w4);
    o = f4fma(o, U1[g * 4 + (g ^ 1)], shflx4(w4, 1));
    o = f4fma(o, U1[g * 4 + (g ^ 2)], shflx4(w4, 2));
    o = f4fma(o, U1[g * 4 + (g ^ 3)], shflx4(w4, 3));

    // store (+ transposed mirror)
    {
        float* p = out + grow * NP + colbase;
        p[0] = o.x; p[1] = o.y; p[2] = o.z; p[3] = o.w;
    }
    if (mirror) {
        out[(colbase + 0) * NP + grow] = o.x;
        out[(colbase + 1) * NP + grow] = o.y;
        out[(colbase + 2) * NP + grow] = o.z;
        out[(colbase + 3) * NP + grow] = o.w;
    }
}

// ---- J diagonal (DI x 6): smem 3-stage with precomputed W ------------------
template <int DI>
__device__ __forceinline__ void path_jdiag(
    const float* __restrict__ rho, float* __restrict__ out,
    const float* __restrict__ thetas,
    int T1, int T2, int t1, int tid, bool mirror,
    float (*sVw)[32], float (*sW)[36], float (*bA)[9], float (*bB)[9])
{
    const int w = tid >> 5, lane = tid & 31;

    float rs[2];
    #pragma unroll
    for (int k = 0; k < 2; k++) {
        int e = tid + 64 * k;
        if (e < DI * 6)
            rs[k] = __ldg(rho + gidx<DI>(T1, T2, e / 6) * NP + gidx<6>(t1, t1, e % 6));
    }
    float* sV = sVw[w];
    compose_V_warp(lane, thetas, sV);
    __syncwarp();

    // precompute W = Lambda^2(V) for both groups (72 entries over 64 threads)
    #pragma unroll
    for (int k = 0; k < 2; k++) {
        int e = tid + 64 * k;
        if (e < 72) {
            int side = e / 36, mn = e % 36, mm = mn / 6, nn = mn % 6;
            const float* U = sVw[w] + side * 16;
            int a = p1of(mm), b = p2of(mm), gg = p1of(nn), d = p2of(nn);
            sW[side][mn] = U[a * 4 + gg] * U[b * 4 + d] - U[a * 4 + d] * U[b * 4 + gg];
        }
    }
    #pragma unroll
    for (int k = 0; k < 2; k++) {
        int e = tid + 64 * k;
        if (e < DI * 6) bA[e / 6][e % 6] = rs[k];
    }
    __syncthreads();

    const float* V1 = sVw[w] + (T1 >> 2) * 16;
    const float* V2 = sVw[w] + (T2 >> 2) * 16;
    const float* WI = sW[T1 >> 2];
    #pragma unroll
    for (int k = 0; k < 2; k++) {
        int e = tid + 64 * k;
        if (e < DI * 6) {
            int mm = e / 6, c = e % 6;
            float acc = 0.f;
            if (DI == 16) {
                const int al = mm >> 2, be = mm & 3;
                #pragma unroll
                for (int ap = 0; ap < 4; ap++) {
                    float s2 = 0.f;
                    #pragma unroll
                    for (int bp = 0; bp < 4; bp++)
                        s2 += V2[be * 4 + bp] * bA[ap * 4 + bp][c];
                    acc += V1[al * 4 + ap] * s2;
                }
            } else {
                #pragma unroll
                for (int n = 0; n < 6; n++)
                    acc += WI[mm * 6 + n] * bA[n][c];
            }
            bB[mm][c] = acc;
        }
    }
    __syncthreads();

    const float* WJ = sW[t1 >> 2];
    #pragma unroll
    for (int k = 0; k < 2; k++) {
        int e = tid + 64 * k;
        if (e < DI * 6) {
            int mm = e / 6, c = e % 6;
            float acc = 0.f;
            #pragma unroll
            for (int n = 0; n < 6; n++)
                acc += WJ[c * 6 + n] * bB[mm][n];
            const int gr = gidx<DI>(T1, T2, mm);
            const int gc = gidx<6>(t1, t1, c);
            out[gr * NP + gc] = acc;
            if (mirror) out[gc * NP + gr] = acc;
        }
    }
}

__global__ void __launch_bounds__(64, 16)
rbs_kernel(const float* __restrict__ rho, float* __restrict__ out,
           const float* __restrict__ thetas)
{
    __shared__ __align__(16) float sVw[2][32];
    __shared__ __align__(16) float4 sY[64];
    __shared__ float sW[2][36];
    __shared__ float bA[16][9], bB[16][9];

    const int tid = threadIdx.x;

    // decode upper-triangular pair (I <= J)
    const int k = blockIdx.x;
    int I = (int)((73.0f - sqrtf(5329.0f - 8.0f * (float)k)) * 0.5f);
    while (tri_base(I + 1) <= k) ++I;
    while (tri_base(I) > k) --I;
    const int J = I + (k - tri_base(I));
    const bool mirror = (I != J);

    int T1, T2, DI, t1, t2, DJ;
    decode_block(I, T1, T2, DI);
    decode_block(J, t1, t2, DJ);

    if (DJ == 16) {
        // I <= J and J cross => I cross too
        path_cross16(rho, out, thetas, T1, T2, t1, t2, tid, mirror, sVw, sY);
    } else if (DI == 16) {
        path_jdiag<16>(rho, out, thetas, T1, T2, t1, tid, mirror, sVw, sW, bA, bB);
    } else {
        path_jdiag< 6>(rho, out, thetas, T1, T2, t1, tid, mirror, sVw, sW, bA, bB);
    }
}

extern "C" void kernel_launch(void* const* d_in, const int* in_sizes, int n_in,
                              void* d_out, int out_size) {
    // metadata order: rho, thetas, A_stack, B_stack, C_stack, u_idx, p_idx
    const float* rho    = (const float*)d_in[0];
    const float* thetas = (const float*)d_in[1];
    float* out = (float*)d_out;

    rbs_kernel<<<666, 64>>>(rho, out, thetas);
}